// round 6
// baseline (speedup 1.0000x reference)
#include <cuda_runtime.h>
#include <cuda_bf16.h>
#include <cstdint>

// ---------------- problem-size constants (fixed by this problem) -------------
#define MAXN   100000
#define NREL   8
#define INF    128
#define HID    32
#define NCOLS  (NREL*HID)      // 256
#define NGMAX  64
#define EPB    1024            // edges per block in scatter2

// ---------------- device scratch (static: no allocations allowed) ------------
// NOTE: several arrays rely on "self-reset" for graph replay: they are zero at
// module load, and every consumer kernel resets them for the next replay.
__device__ __align__(128) float g_y1[(size_t)MAXN * NCOLS];   // x @ [W1_0..W1_7]
__device__ __align__(128) float g_h1[(size_t)MAXN * HID];     // scatter1 accum (reset by k_relu)
__device__ __align__(128) float g_h1b[(size_t)MAXN * HID];    // relu output
__device__ __align__(128) float g_rso[NREL * MAXN];           // rsqrt(max(deg_out,1))
__device__ __align__(128) float g_rsi[NREL * MAXN];           // rsqrt(max(deg_in,1))
__device__ __align__(128) int   g_dego[NREL * MAXN];          // reset by k_prep
__device__ __align__(128) int   g_degi[NREL * MAXN];          // reset by k_prep
__device__ __align__(128) int   g_cnt[NGMAX];                 // reset by k_relu
__device__ __align__(128) float g_inv[NGMAX];                 // 1/max(cnt,1)
__device__ __align__(128) float g_V[NREL * HID * 2];          // W2_r @ Wc
// bf16 hi/lo weight image, [n][k] layout (k contiguous, 256B/row):
// [0,64K) = B_hi (256 n-rows x 128 k), [64K,128K) = B_lo
__device__ __align__(128) unsigned char g_wimg[131072];

// ---------------- K2: degrees + per-graph node counts ------------------------
__global__ void k_deg(const int* __restrict__ src, const int* __restrict__ dst,
                      const int* __restrict__ gids, int n_nodes, int n_edges) {
    int i = blockIdx.x * blockDim.x + threadIdx.x;
    int te = NREL * n_edges;
    if (i < te) {
        int r = i / n_edges;
        atomicAdd(&g_dego[r * n_nodes + src[i]], 1);
        atomicAdd(&g_degi[r * n_nodes + dst[i]], 1);
    } else if (i < te + n_nodes) {
        atomicAdd(&g_cnt[gids[i - te]], 1);
    }
}

// ---------------- K3: rsqrt tables, V_r = W2_r @ Wc, out init; deg reset ------
__global__ void k_prep(const float* __restrict__ W2, const float* __restrict__ Wc,
                       const float* __restrict__ b2, const float* __restrict__ bc,
                       float* __restrict__ out, int n_nodes, int n_graphs) {
    int i = blockIdx.x * blockDim.x + threadIdx.x;
    int t1 = NREL * n_nodes;
    if (i < t1) {
        g_rso[i] = rsqrtf((float)max(g_dego[i], 1));
        g_rsi[i] = rsqrtf((float)max(g_degi[i], 1));
        g_dego[i] = 0;                 // self-reset for next graph replay
        g_degi[i] = 0;
    } else if (i < t1 + NREL * HID * 2) {
        int v = i - t1;
        int r = v >> 6, f = (v >> 1) & 31, o = v & 1;
        float s = 0.f;
        #pragma unroll
        for (int j = 0; j < HID; j++) s += W2[r * (HID * HID) + f * HID + j] * Wc[j * 2 + o];
        g_V[v] = s;
    } else if (i < t1 + NREL * HID * 2 + 2 * n_graphs) {
        int u = i - t1 - NREL * HID * 2;
        int g = u >> 1, o = u & 1;
        if (o == 0) g_inv[g] = 1.f / (float)max(g_cnt[g], 1);
        float s = 0.f;
        for (int j = 0; j < HID; j++) {
            float bs = 0.f;
            #pragma unroll
            for (int r = 0; r < NREL; r++) bs += b2[r * HID + j];
            s += bs * Wc[j * 2 + o];
        }
        out[u] = bc[o] + (g_cnt[g] > 0 ? s : 0.f);   // empty graph -> pooled = 0
    }
}

// ---------------- K3b: W1 -> bf16 hi/lo image, [n][k] layout ------------------
__global__ void k_wconv(const float* __restrict__ W1) {
    int i = blockIdx.x * blockDim.x + threadIdx.x;   // 0..16383
    if (i >= 256 * 64) return;
    int n = i >> 6, kp = (i & 63);                   // col n, k pair index
    int k = kp * 2;
    int r = n >> 5, f = n & 31;
    float w0 = W1[r * (INF * HID) + k * HID + f];
    float w1 = W1[r * (INF * HID) + (k + 1) * HID + f];
    __nv_bfloat16 h0 = __float2bfloat16(w0);
    __nv_bfloat16 h1 = __float2bfloat16(w1);
    __nv_bfloat16 l0 = __float2bfloat16(w0 - __bfloat162float(h0));
    __nv_bfloat16 l1 = __float2bfloat16(w1 - __bfloat162float(h1));
    uint32_t off = (uint32_t)n * 256u + (uint32_t)k * 2u;
    __nv_bfloat162 hv; hv.x = h0; hv.y = h1;
    __nv_bfloat162 lv; lv.x = l0; lv.y = l1;
    *(__nv_bfloat162*)(g_wimg + off) = hv;
    *(__nv_bfloat162*)(g_wimg + 65536 + off) = lv;
}

// ---------------- K4: HMMA GEMM  y1 = x @ [W1_0..W1_7] ------------------------
// CTA: 128 nodes x 128 cols; K split into 2 chunks of 64 (smem 72KB -> 2 CTA/SM).
// 8 warps (4M x 2N), warp tile 32x64. bf16 hi/lo split: 3 accumulating passes.
// Row stride 144B: (row*36 + word) mod 32 hits all banks -> conflict-free LDS.
#define SROW  144                    // bytes per smem row (64 k bf16 + 16B pad)
#define SA_H  0
#define SA_L  (128 * SROW)           // 18432
#define SB_H  (2 * 128 * SROW)       // 36864
#define SB_L  (3 * 128 * SROW)       // 55296
#define SMEM_G (4 * 128 * SROW)      // 73728

__device__ __forceinline__ void mma16816(float* c, const uint32_t* a, const uint32_t* b) {
    asm volatile("mma.sync.aligned.m16n8k16.row.col.f32.bf16.bf16.f32 "
        "{%0,%1,%2,%3}, {%4,%5,%6,%7}, {%8,%9}, {%0,%1,%2,%3};"
        : "+f"(c[0]), "+f"(c[1]), "+f"(c[2]), "+f"(c[3])
        : "r"(a[0]), "r"(a[1]), "r"(a[2]), "r"(a[3]), "r"(b[0]), "r"(b[1]));
}

__global__ __launch_bounds__(256, 2) void k_gemm_mma(const float* __restrict__ x,
                                                     int n_nodes) {
    extern __shared__ unsigned char smem[];
    int t = threadIdx.x, wid = t >> 5, lid = t & 31;
    int gid = lid >> 2, tid4 = lid & 3;
    int node0 = blockIdx.x * 128;
    int cbase = blockIdx.y * 128;

    int mrow0 = (wid & 3) * 32;
    int ncol0 = (wid >> 2) * 64;
    float acc[2][8][4];
    #pragma unroll
    for (int mi = 0; mi < 2; mi++)
        #pragma unroll
        for (int ni = 0; ni < 8; ni++)
            #pragma unroll
            for (int q = 0; q < 4; q++) acc[mi][ni][q] = 0.f;

    #pragma unroll
    for (int kc = 0; kc < 2; kc++) {
        int kofs = kc * 64;
        if (kc) __syncthreads();        // protect smem reuse across chunks
        // ---- stage A (x tile chunk) as bf16 hi/lo -----------------------------
        #pragma unroll
        for (int p = 0; p < 8; p++) {
            int idx = p * 256 + t;               // 0..2047
            int m = idx >> 4, k = (idx & 15) * 4;
            int gn = node0 + m;
            float4 v = make_float4(0.f, 0.f, 0.f, 0.f);
            if (gn < n_nodes) v = *(const float4*)(x + (size_t)gn * INF + kofs + k);
            __nv_bfloat16 h0 = __float2bfloat16(v.x), h1 = __float2bfloat16(v.y);
            __nv_bfloat16 h2 = __float2bfloat16(v.z), h3 = __float2bfloat16(v.w);
            __nv_bfloat16 l0 = __float2bfloat16(v.x - __bfloat162float(h0));
            __nv_bfloat16 l1 = __float2bfloat16(v.y - __bfloat162float(h1));
            __nv_bfloat16 l2 = __float2bfloat16(v.z - __bfloat162float(h2));
            __nv_bfloat16 l3 = __float2bfloat16(v.w - __bfloat162float(h3));
            __nv_bfloat162 a, b;
            a.x = h0; a.y = h1; b.x = h2; b.y = h3;
            uint2 hp; hp.x = *(uint32_t*)&a; hp.y = *(uint32_t*)&b;
            a.x = l0; a.y = l1; b.x = l2; b.y = l3;
            uint2 lp; lp.x = *(uint32_t*)&a; lp.y = *(uint32_t*)&b;
            *(uint2*)(smem + SA_H + m * SROW + k * 2) = hp;
            *(uint2*)(smem + SA_L + m * SROW + k * 2) = lp;
        }
        // ---- stage B (weight image chunk, pre-converted bf16 hi/lo) ------------
        {
            const unsigned char* bh = g_wimg + (size_t)blockIdx.y * 32768;
            const unsigned char* bl = bh + 65536;
            #pragma unroll
            for (int p = 0; p < 4; p++) {
                int idx = p * 256 + t;           // 0..1023
                int n = idx >> 3, c = idx & 7;
                uint32_t so = (uint32_t)n * 256u + (uint32_t)kofs * 2u + (uint32_t)c * 16u;
                *(uint4*)(smem + SB_H + n * SROW + c * 16) = *(const uint4*)(bh + so);
                *(uint4*)(smem + SB_L + n * SROW + c * 16) = *(const uint4*)(bl + so);
            }
        }
        __syncthreads();

        #pragma unroll
        for (int pass = 0; pass < 3; pass++) {
            int ab = (pass == 2) ? SA_L : SA_H;
            int bb = (pass == 1) ? SB_L : SB_H;
            const unsigned char* ap = smem + ab + (mrow0 + gid) * SROW + tid4 * 4;
            const unsigned char* bp = smem + bb + (ncol0 + gid) * SROW + tid4 * 4;
            #pragma unroll
            for (int ks = 0; ks < 4; ks++) {
                int kb = ks * 32;
                uint32_t afr[2][4];
                #pragma unroll
                for (int mi = 0; mi < 2; mi++) {
                    const unsigned char* a0 = ap + mi * 16 * SROW + kb;
                    afr[mi][0] = *(const uint32_t*)(a0);
                    afr[mi][1] = *(const uint32_t*)(a0 + 8 * SROW);
                    afr[mi][2] = *(const uint32_t*)(a0 + 16);
                    afr[mi][3] = *(const uint32_t*)(a0 + 8 * SROW + 16);
                }
                #pragma unroll
                for (int ni = 0; ni < 8; ni++) {
                    const unsigned char* b0 = bp + ni * 8 * SROW + kb;
                    uint32_t bfr[2];
                    bfr[0] = *(const uint32_t*)(b0);
                    bfr[1] = *(const uint32_t*)(b0 + 16);
                    mma16816(acc[0][ni], afr[0], bfr);
                    mma16816(acc[1][ni], afr[1], bfr);
                }
            }
        }
    }

    // ---- epilogue: write y1 ----------------------------------------------------
    #pragma unroll
    for (int mi = 0; mi < 2; mi++) {
        int r0 = node0 + mrow0 + mi * 16 + gid;
        #pragma unroll
        for (int ni = 0; ni < 8; ni++) {
            int col = cbase + ncol0 + ni * 8 + tid4 * 2;
            if (r0 < n_nodes)
                *(float2*)(g_y1 + (size_t)r0 * NCOLS + col) =
                    make_float2(acc[mi][ni][0], acc[mi][ni][1]);
            if (r0 + 8 < n_nodes)
                *(float2*)(g_y1 + (size_t)(r0 + 8) * NCOLS + col) =
                    make_float2(acc[mi][ni][2], acc[mi][ni][3]);
        }
    }
}

// ---------------- K5: layer-1 edge scatter (both deg scales folded) ----------
__global__ void k_scatter1(const int* __restrict__ src, const int* __restrict__ dst,
                           int n_nodes, int n_edges) {
    int i = blockIdx.x * blockDim.x + threadIdx.x;
    int tot = NREL * n_edges * 8;
    if (i >= tot) return;
    int e = i >> 3, q = i & 7;
    int r = e / n_edges;
    int s = src[e], d = dst[e];
    float sc = g_rso[r * n_nodes + s] * g_rsi[r * n_nodes + d];
    float4 v = *(const float4*)(g_y1 + (size_t)s * NCOLS + r * HID + q * 4);
    v.x *= sc; v.y *= sc; v.z *= sc; v.w *= sc;
    atomicAdd((float4*)(g_h1 + (size_t)d * HID + q * 4), v);
}

// ---------------- K6: bias + relu (h1 -> h1b); resets h1 and cnt --------------
__global__ void k_relu(const float* __restrict__ b1, int n_nodes) {
    __shared__ float bs[HID];
    if (threadIdx.x < HID) {
        float s = 0.f;
        #pragma unroll
        for (int r = 0; r < NREL; r++) s += b1[r * HID + threadIdx.x];
        bs[threadIdx.x] = s;
    }
    __syncthreads();
    int i = blockIdx.x * blockDim.x + threadIdx.x;
    if (i < n_nodes * HID) {
        g_h1b[i] = fmaxf(g_h1[i] + bs[i & 31], 0.f);
        g_h1[i] = 0.f;                  // self-reset for next graph replay
    }
    if (blockIdx.x == 0 && threadIdx.x < NGMAX) g_cnt[threadIdx.x] = 0;
}

// -------- K7: fused layer-2 + mean-pool + classifier (edge -> out[64,2]) -----
__global__ __launch_bounds__(256) void k_scatter2(const int* __restrict__ src,
                                                  const int* __restrict__ dst,
                                                  const int* __restrict__ gids,
                                                  float* __restrict__ out,
                                                  int n_nodes, int n_edges) {
    __shared__ float zs[NGMAX * 2];
    __shared__ float Vs[NREL * HID * 2];
    __shared__ float inv_s[NGMAX];
    int t = threadIdx.x;
    if (t < NGMAX * 2) zs[t] = 0.f;
    for (int i = t; i < NREL * HID * 2; i += 256) Vs[i] = g_V[i];
    if (t < NGMAX) inv_s[t] = g_inv[t];
    __syncthreads();

    int te = NREL * n_edges;
    int e0 = blockIdx.x * EPB;
    #pragma unroll
    for (int it = 0; it < EPB / 256; it++) {
        int e = e0 + it * 256 + t;
        if (e < te) {
            int r = e / n_edges;
            int s = src[e], d = dst[e];
            int g = gids[d];
            float coeff = g_rso[r * n_nodes + s] * g_rsi[r * n_nodes + d] * inv_s[g];
            const float4* hp = (const float4*)(g_h1b + (size_t)s * HID);
            const float* vp = Vs + r * (HID * 2);
            float a0 = 0.f, a1 = 0.f;
            #pragma unroll
            for (int q = 0; q < 8; q++) {
                float4 hv = hp[q];
                a0 += hv.x * vp[q * 8 + 0] + hv.y * vp[q * 8 + 2] +
                      hv.z * vp[q * 8 + 4] + hv.w * vp[q * 8 + 6];
                a1 += hv.x * vp[q * 8 + 1] + hv.y * vp[q * 8 + 3] +
                      hv.z * vp[q * 8 + 5] + hv.w * vp[q * 8 + 7];
            }
            atomicAdd(&zs[g * 2 + 0], a0 * coeff);
            atomicAdd(&zs[g * 2 + 1], a1 * coeff);
        }
    }
    __syncthreads();
    if (t < NGMAX * 2) atomicAdd(&out[t], zs[t]);
}

// ---------------- launch ------------------------------------------------------
extern "C" void kernel_launch(void* const* d_in, const int* in_sizes, int n_in,
                              void* d_out, int out_size) {
    int off = (n_in >= 11) ? 1 : 0;
    const float* x   = (const float*)d_in[0];
    const int*   src = (const int*)d_in[1];
    const int*   dst = (const int*)d_in[2];
    const int*   gid = (const int*)d_in[3];
    const float* W1  = (const float*)d_in[4 + off];
    const float* b1  = (const float*)d_in[5 + off];
    const float* W2  = (const float*)d_in[6 + off];
    const float* b2  = (const float*)d_in[7 + off];
    const float* Wc  = (const float*)d_in[8 + off];
    const float* bc  = (const float*)d_in[9 + off];
    float* out = (float*)d_out;

    int n_nodes  = in_sizes[3];
    int n_edges  = in_sizes[1] / NREL;
    int n_graphs = out_size / 2;

    cudaFuncSetAttribute(k_gemm_mma, cudaFuncAttributeMaxDynamicSharedMemorySize,
                         SMEM_G);

    k_wconv<<<64, 256>>>(W1);

    int tot1 = NREL * n_edges + n_nodes;
    k_deg<<<(tot1 + 255) / 256, 256>>>(src, dst, gid, n_nodes, n_edges);

    int tot2 = NREL * n_nodes + NREL * HID * 2 + 2 * n_graphs;
    k_prep<<<(tot2 + 255) / 256, 256>>>(W2, Wc, b2, bc, out, n_nodes, n_graphs);

    dim3 g4((n_nodes + 127) / 128, 2);
    k_gemm_mma<<<g4, 256, SMEM_G>>>(x, n_nodes);

    int tot5 = NREL * n_edges * 8;
    k_scatter1<<<(tot5 + 255) / 256, 256>>>(src, dst, n_nodes, n_edges);

    int tot6 = HID * n_nodes;
    k_relu<<<(tot6 + 255) / 256, 256>>>(b1, n_nodes);

    k_scatter2<<<(NREL * n_edges + EPB - 1) / EPB, 256>>>(src, dst, gid, out,
                                                          n_nodes, n_edges);
}

// round 7
// speedup vs baseline: 1.1873x; 1.1873x over previous
#include <cuda_runtime.h>
#include <cuda_bf16.h>
#include <cstdint>

// ---------------- problem-size constants (fixed by this problem) -------------
#define MAXN   100000
#define NREL   8
#define INF    128
#define HID    32
#define NCOLS  (NREL*HID)      // 256
#define NGMAX  64
#define EPB    1024            // edges per block in scatter2

// ---------------- device scratch (static: no allocations allowed) ------------
// Self-reset for graph replay: zero at module load; every consumer kernel
// resets what it consumed so the next replay sees zeros again.
__device__ __align__(128) float g_y1[(size_t)MAXN * NCOLS];   // x @ [W1_0..W1_7]
__device__ __align__(128) float g_h1[(size_t)MAXN * HID];     // scatter1 accum (reset by k_relu)
__device__ __align__(128) float g_h1b[(size_t)MAXN * HID];    // relu output
__device__ __align__(128) float g_rso[NREL * MAXN];           // rsqrt(max(deg_out,1))
__device__ __align__(128) float g_rsi[NREL * MAXN];           // rsqrt(max(deg_in,1))
__device__ __align__(128) int   g_dego[NREL * MAXN];          // reset by k_prep
__device__ __align__(128) int   g_degi[NREL * MAXN];          // reset by k_prep
__device__ __align__(128) int   g_cnt[NGMAX];                 // reset by k_relu
__device__ __align__(128) float g_inv[NGMAX];                 // 1/max(cnt,1)
__device__ __align__(128) float g_V[NREL * HID * 2];          // W2_r @ Wc
// bf16 hi/lo weight image, [n][k] layout (k contiguous, 256B/row):
// [0,64K) = B_hi (256 n-rows x 128 k), [64K,128K) = B_lo
__device__ __align__(128) unsigned char g_wimg[131072];

// ---------------- K2: degrees + per-graph node counts ------------------------
__global__ void k_deg(const int* __restrict__ src, const int* __restrict__ dst,
                      const int* __restrict__ gids, int n_nodes, int n_edges) {
    int i = blockIdx.x * blockDim.x + threadIdx.x;
    int te = NREL * n_edges;
    if (i < te) {
        int r = i / n_edges;
        atomicAdd(&g_dego[r * n_nodes + src[i]], 1);
        atomicAdd(&g_degi[r * n_nodes + dst[i]], 1);
    } else if (i < te + n_nodes) {
        atomicAdd(&g_cnt[gids[i - te]], 1);
    }
}

// ---------------- K3: rsqrt tables, V_r = W2_r @ Wc, out init; deg reset ------
__global__ void k_prep(const float* __restrict__ W2, const float* __restrict__ Wc,
                       const float* __restrict__ b2, const float* __restrict__ bc,
                       float* __restrict__ out, int n_nodes, int n_graphs) {
    int i = blockIdx.x * blockDim.x + threadIdx.x;
    int t1 = NREL * n_nodes;
    if (i < t1) {
        g_rso[i] = rsqrtf((float)max(g_dego[i], 1));
        g_rsi[i] = rsqrtf((float)max(g_degi[i], 1));
        g_dego[i] = 0;                 // self-reset for next graph replay
        g_degi[i] = 0;
    } else if (i < t1 + NREL * HID * 2) {
        int v = i - t1;
        int r = v >> 6, f = (v >> 1) & 31, o = v & 1;
        float s = 0.f;
        #pragma unroll
        for (int j = 0; j < HID; j++) s += W2[r * (HID * HID) + f * HID + j] * Wc[j * 2 + o];
        g_V[v] = s;
    } else if (i < t1 + NREL * HID * 2 + 2 * n_graphs) {
        int u = i - t1 - NREL * HID * 2;
        int g = u >> 1, o = u & 1;
        if (o == 0) g_inv[g] = 1.f / (float)max(g_cnt[g], 1);
        float s = 0.f;
        for (int j = 0; j < HID; j++) {
            float bs = 0.f;
            #pragma unroll
            for (int r = 0; r < NREL; r++) bs += b2[r * HID + j];
            s += bs * Wc[j * 2 + o];
        }
        out[u] = bc[o] + (g_cnt[g] > 0 ? s : 0.f);   // empty graph -> pooled = 0
    }
}

// ---------------- K3b: W1 -> bf16 hi/lo image, [n][k] layout ------------------
__global__ void k_wconv(const float* __restrict__ W1) {
    int i = blockIdx.x * blockDim.x + threadIdx.x;   // 0..16383
    if (i >= 256 * 64) return;
    int n = i >> 6, kp = (i & 63);                   // col n, k pair index
    int k = kp * 2;
    int r = n >> 5, f = n & 31;
    float w0 = W1[r * (INF * HID) + k * HID + f];
    float w1 = W1[r * (INF * HID) + (k + 1) * HID + f];
    __nv_bfloat16 h0 = __float2bfloat16(w0);
    __nv_bfloat16 h1 = __float2bfloat16(w1);
    __nv_bfloat16 l0 = __float2bfloat16(w0 - __bfloat162float(h0));
    __nv_bfloat16 l1 = __float2bfloat16(w1 - __bfloat162float(h1));
    uint32_t off = (uint32_t)n * 256u + (uint32_t)k * 2u;
    __nv_bfloat162 hv; hv.x = h0; hv.y = h1;
    __nv_bfloat162 lv; lv.x = l0; lv.y = l1;
    *(__nv_bfloat162*)(g_wimg + off) = hv;
    *(__nv_bfloat162*)(g_wimg + 65536 + off) = lv;
}

// ---------------- K4: HMMA GEMM  y1 = x @ [W1_0..W1_7] ------------------------
// CTA: 128 nodes x 256 cols (ALL cols -> x read once). 512 threads, 16 warps
// (4M x 4N), warp tile 32x64. K split into 2 chunks of 64 (smem 108KB).
// bf16 hi/lo split, fragment-shared: per k-step load a_hi/a_lo once, per ni
// load b_hi/b_lo once, issue hh + lh + hl on those fragments.
// Row stride 144B: (row*36 + word) mod 32 covers all banks -> conflict-free.
#define SROW  144
#define SA_H  0
#define SA_L  (128 * SROW)               // 18432
#define SB_H  (2 * 128 * SROW)           // 36864
#define SB_L  (SB_H + 256 * SROW)        // 73728
#define SMEM_G (SB_L + 256 * SROW)       // 110592

__device__ __forceinline__ void mma16816(float* c, const uint32_t* a, const uint32_t* b) {
    asm volatile("mma.sync.aligned.m16n8k16.row.col.f32.bf16.bf16.f32 "
        "{%0,%1,%2,%3}, {%4,%5,%6,%7}, {%8,%9}, {%0,%1,%2,%3};"
        : "+f"(c[0]), "+f"(c[1]), "+f"(c[2]), "+f"(c[3])
        : "r"(a[0]), "r"(a[1]), "r"(a[2]), "r"(a[3]), "r"(b[0]), "r"(b[1]));
}

__global__ __launch_bounds__(512, 1) void k_gemm_mma(const float* __restrict__ x,
                                                     int n_nodes) {
    extern __shared__ unsigned char smem[];
    int t = threadIdx.x, wid = t >> 5, lid = t & 31;
    int gid = lid >> 2, tid4 = lid & 3;
    int node0 = blockIdx.x * 128;

    int mrow0 = (wid & 3) * 32;          // 4 M-groups
    int ncol0 = (wid >> 2) * 64;         // 4 N-groups
    float acc[2][8][4];
    #pragma unroll
    for (int mi = 0; mi < 2; mi++)
        #pragma unroll
        for (int ni = 0; ni < 8; ni++)
            #pragma unroll
            for (int q = 0; q < 4; q++) acc[mi][ni][q] = 0.f;

    #pragma unroll
    for (int kc = 0; kc < 2; kc++) {
        int kofs = kc * 64;
        if (kc) __syncthreads();
        // ---- stage A (x chunk) as bf16 hi/lo: 128 rows x 64 k ------------------
        #pragma unroll
        for (int p = 0; p < 4; p++) {
            int idx = p * 512 + t;               // 0..2047
            int m = idx >> 4, k = (idx & 15) * 4;
            int gn = node0 + m;
            float4 v = make_float4(0.f, 0.f, 0.f, 0.f);
            if (gn < n_nodes) v = *(const float4*)(x + (size_t)gn * INF + kofs + k);
            __nv_bfloat16 h0 = __float2bfloat16(v.x), h1 = __float2bfloat16(v.y);
            __nv_bfloat16 h2 = __float2bfloat16(v.z), h3 = __float2bfloat16(v.w);
            __nv_bfloat16 l0 = __float2bfloat16(v.x - __bfloat162float(h0));
            __nv_bfloat16 l1 = __float2bfloat16(v.y - __bfloat162float(h1));
            __nv_bfloat16 l2 = __float2bfloat16(v.z - __bfloat162float(h2));
            __nv_bfloat16 l3 = __float2bfloat16(v.w - __bfloat162float(h3));
            __nv_bfloat162 a, b;
            a.x = h0; a.y = h1; b.x = h2; b.y = h3;
            uint2 hp; hp.x = *(uint32_t*)&a; hp.y = *(uint32_t*)&b;
            a.x = l0; a.y = l1; b.x = l2; b.y = l3;
            uint2 lp; lp.x = *(uint32_t*)&a; lp.y = *(uint32_t*)&b;
            *(uint2*)(smem + SA_H + m * SROW + k * 2) = hp;
            *(uint2*)(smem + SA_L + m * SROW + k * 2) = lp;
        }
        // ---- stage B chunk (pre-converted bf16 hi/lo): 256 rows x 64 k ----------
        {
            const unsigned char* bh = g_wimg;
            const unsigned char* bl = g_wimg + 65536;
            #pragma unroll
            for (int p = 0; p < 4; p++) {
                int idx = p * 512 + t;           // 0..2047
                int n = idx >> 3, c = idx & 7;
                uint32_t so = (uint32_t)n * 256u + (uint32_t)kofs * 2u + (uint32_t)c * 16u;
                *(uint4*)(smem + SB_H + n * SROW + c * 16) = *(const uint4*)(bh + so);
                *(uint4*)(smem + SB_L + n * SROW + c * 16) = *(const uint4*)(bl + so);
            }
        }
        __syncthreads();

        const unsigned char* aph = smem + SA_H + (mrow0 + gid) * SROW + tid4 * 4;
        const unsigned char* apl = smem + SA_L + (mrow0 + gid) * SROW + tid4 * 4;
        const unsigned char* bph = smem + SB_H + (ncol0 + gid) * SROW + tid4 * 4;
        const unsigned char* bpl = smem + SB_L + (ncol0 + gid) * SROW + tid4 * 4;
        #pragma unroll
        for (int ks = 0; ks < 4; ks++) {
            int kb = ks * 32;
            uint32_t ah[2][4], al[2][4];
            #pragma unroll
            for (int mi = 0; mi < 2; mi++) {
                const unsigned char* a0 = aph + mi * 16 * SROW + kb;
                ah[mi][0] = *(const uint32_t*)(a0);
                ah[mi][1] = *(const uint32_t*)(a0 + 8 * SROW);
                ah[mi][2] = *(const uint32_t*)(a0 + 16);
                ah[mi][3] = *(const uint32_t*)(a0 + 8 * SROW + 16);
                const unsigned char* a1 = apl + mi * 16 * SROW + kb;
                al[mi][0] = *(const uint32_t*)(a1);
                al[mi][1] = *(const uint32_t*)(a1 + 8 * SROW);
                al[mi][2] = *(const uint32_t*)(a1 + 16);
                al[mi][3] = *(const uint32_t*)(a1 + 8 * SROW + 16);
            }
            #pragma unroll
            for (int ni = 0; ni < 8; ni++) {
                const unsigned char* b0 = bph + ni * 8 * SROW + kb;
                const unsigned char* b1 = bpl + ni * 8 * SROW + kb;
                uint32_t bh2[2], bl2[2];
                bh2[0] = *(const uint32_t*)(b0);
                bh2[1] = *(const uint32_t*)(b0 + 16);
                bl2[0] = *(const uint32_t*)(b1);
                bl2[1] = *(const uint32_t*)(b1 + 16);
                #pragma unroll
                for (int mi = 0; mi < 2; mi++) {
                    mma16816(acc[mi][ni], ah[mi], bh2);   // hi*hi
                    mma16816(acc[mi][ni], al[mi], bh2);   // lo*hi
                    mma16816(acc[mi][ni], ah[mi], bl2);   // hi*lo
                }
            }
        }
    }

    // ---- epilogue: write y1 ----------------------------------------------------
    #pragma unroll
    for (int mi = 0; mi < 2; mi++) {
        int r0 = node0 + mrow0 + mi * 16 + gid;
        #pragma unroll
        for (int ni = 0; ni < 8; ni++) {
            int col = ncol0 + ni * 8 + tid4 * 2;
            if (r0 < n_nodes)
                *(float2*)(g_y1 + (size_t)r0 * NCOLS + col) =
                    make_float2(acc[mi][ni][0], acc[mi][ni][1]);
            if (r0 + 8 < n_nodes)
                *(float2*)(g_y1 + (size_t)(r0 + 8) * NCOLS + col) =
                    make_float2(acc[mi][ni][2], acc[mi][ni][3]);
        }
    }
}

// ---------------- K5: layer-1 edge scatter (both deg scales folded) ----------
__global__ void k_scatter1(const int* __restrict__ src, const int* __restrict__ dst,
                           int n_nodes, int n_edges) {
    int i = blockIdx.x * blockDim.x + threadIdx.x;
    int tot = NREL * n_edges * 8;
    if (i >= tot) return;
    int e = i >> 3, q = i & 7;
    int r = e / n_edges;
    int s = src[e], d = dst[e];
    float sc = g_rso[r * n_nodes + s] * g_rsi[r * n_nodes + d];
    float4 v = *(const float4*)(g_y1 + (size_t)s * NCOLS + r * HID + q * 4);
    v.x *= sc; v.y *= sc; v.z *= sc; v.w *= sc;
    atomicAdd((float4*)(g_h1 + (size_t)d * HID + q * 4), v);
}

// ---------------- K6: bias + relu (h1 -> h1b); resets h1 and cnt --------------
__global__ void k_relu(const float* __restrict__ b1, int n_nodes) {
    __shared__ float bs[HID];
    if (threadIdx.x < HID) {
        float s = 0.f;
        #pragma unroll
        for (int r = 0; r < NREL; r++) s += b1[r * HID + threadIdx.x];
        bs[threadIdx.x] = s;
    }
    __syncthreads();
    int i = blockIdx.x * blockDim.x + threadIdx.x;
    if (i < n_nodes * HID) {
        g_h1b[i] = fmaxf(g_h1[i] + bs[i & 31], 0.f);
        g_h1[i] = 0.f;                  // self-reset for next graph replay
    }
    if (blockIdx.x == 0 && threadIdx.x < NGMAX) g_cnt[threadIdx.x] = 0;
}

// -------- K7: fused layer-2 + mean-pool + classifier (edge -> out[64,2]) -----
__global__ __launch_bounds__(256) void k_scatter2(const int* __restrict__ src,
                                                  const int* __restrict__ dst,
                                                  const int* __restrict__ gids,
                                                  float* __restrict__ out,
                                                  int n_nodes, int n_edges) {
    __shared__ float zs[NGMAX * 2];
    __shared__ float Vs[NREL * HID * 2];
    __shared__ float inv_s[NGMAX];
    int t = threadIdx.x;
    if (t < NGMAX * 2) zs[t] = 0.f;
    for (int i = t; i < NREL * HID * 2; i += 256) Vs[i] = g_V[i];
    if (t < NGMAX) inv_s[t] = g_inv[t];
    __syncthreads();

    int te = NREL * n_edges;
    int e0 = blockIdx.x * EPB;
    #pragma unroll
    for (int it = 0; it < EPB / 256; it++) {
        int e = e0 + it * 256 + t;
        if (e < te) {
            int r = e / n_edges;
            int s = src[e], d = dst[e];
            int g = gids[d];
            float coeff = g_rso[r * n_nodes + s] * g_rsi[r * n_nodes + d] * inv_s[g];
            const float4* hp = (const float4*)(g_h1b + (size_t)s * HID);
            const float* vp = Vs + r * (HID * 2);
            float a0 = 0.f, a1 = 0.f;
            #pragma unroll
            for (int q = 0; q < 8; q++) {
                float4 hv = hp[q];
                a0 += hv.x * vp[q * 8 + 0] + hv.y * vp[q * 8 + 2] +
                      hv.z * vp[q * 8 + 4] + hv.w * vp[q * 8 + 6];
                a1 += hv.x * vp[q * 8 + 1] + hv.y * vp[q * 8 + 3] +
                      hv.z * vp[q * 8 + 5] + hv.w * vp[q * 8 + 7];
            }
            atomicAdd(&zs[g * 2 + 0], a0 * coeff);
            atomicAdd(&zs[g * 2 + 1], a1 * coeff);
        }
    }
    __syncthreads();
    if (t < NGMAX * 2) atomicAdd(&out[t], zs[t]);
}

// ---------------- launch ------------------------------------------------------
extern "C" void kernel_launch(void* const* d_in, const int* in_sizes, int n_in,
                              void* d_out, int out_size) {
    int off = (n_in >= 11) ? 1 : 0;
    const float* x   = (const float*)d_in[0];
    const int*   src = (const int*)d_in[1];
    const int*   dst = (const int*)d_in[2];
    const int*   gid = (const int*)d_in[3];
    const float* W1  = (const float*)d_in[4 + off];
    const float* b1  = (const float*)d_in[5 + off];
    const float* W2  = (const float*)d_in[6 + off];
    const float* b2  = (const float*)d_in[7 + off];
    const float* Wc  = (const float*)d_in[8 + off];
    const float* bc  = (const float*)d_in[9 + off];
    float* out = (float*)d_out;

    int n_nodes  = in_sizes[3];
    int n_edges  = in_sizes[1] / NREL;
    int n_graphs = out_size / 2;

    cudaFuncSetAttribute(k_gemm_mma, cudaFuncAttributeMaxDynamicSharedMemorySize,
                         SMEM_G);

    k_wconv<<<64, 256>>>(W1);

    int tot1 = NREL * n_edges + n_nodes;
    k_deg<<<(tot1 + 255) / 256, 256>>>(src, dst, gid, n_nodes, n_edges);

    int tot2 = NREL * n_nodes + NREL * HID * 2 + 2 * n_graphs;
    k_prep<<<(tot2 + 255) / 256, 256>>>(W2, Wc, b2, bc, out, n_nodes, n_graphs);

    k_gemm_mma<<<(n_nodes + 127) / 128, 512, SMEM_G>>>(x, n_nodes);

    int tot5 = NREL * n_edges * 8;
    k_scatter1<<<(tot5 + 255) / 256, 256>>>(src, dst, n_nodes, n_edges);

    int tot6 = HID * n_nodes;
    k_relu<<<(tot6 + 255) / 256, 256>>>(b1, n_nodes);

    k_scatter2<<<(NREL * n_edges + EPB - 1) / EPB, 256>>>(src, dst, gid, out,
                                                          n_nodes, n_edges);
}

// round 8
// speedup vs baseline: 1.1950x; 1.0064x over previous
#include <cuda_runtime.h>
#include <cuda_bf16.h>
#include <cstdint>

// ---------------- problem-size constants (fixed by this problem) -------------
#define MAXN   100000
#define NREL   8
#define INF    128
#define HID    32
#define NCOLS  (NREL*HID)      // 256
#define NGMAX  64
#define EPB    1024            // edges per block in scatter2

// ---------------- device scratch (static: no allocations allowed) ------------
// Self-reset for graph replay: zero at module load; every consumer kernel
// resets what it consumed so the next replay sees zeros again.
__device__ __align__(128) float g_y1[(size_t)MAXN * NCOLS];   // x @ [W1_0..W1_7]
__device__ __align__(128) float g_h1[(size_t)MAXN * HID];     // scatter1 accum (reset by k_relu)
__device__ __align__(128) float g_h1b[(size_t)MAXN * HID];    // relu output
__device__ __align__(128) float g_rso[NREL * MAXN];           // rsqrt(max(deg_out,1))
__device__ __align__(128) float g_rsi[NREL * MAXN];           // rsqrt(max(deg_in,1))
__device__ __align__(128) int   g_dego[NREL * MAXN];          // reset by k_prep
__device__ __align__(128) int   g_degi[NREL * MAXN];          // reset by k_prep
__device__ __align__(128) int   g_cnt[NGMAX];                 // reset by k_relu
__device__ __align__(128) float g_inv[NGMAX];                 // 1/max(cnt,1)
__device__ __align__(128) float g_V[NREL * HID * 2];          // W2_r @ Wc
// bf16 hi/lo weight image, [n][k] layout (k contiguous, 256B/row):
// [0,64K) = B_hi (256 n-rows x 128 k), [64K,128K) = B_lo
__device__ __align__(128) unsigned char g_wimg[131072];

__device__ __forceinline__ uint32_t smem_u32(const void* p) {
    uint32_t a;
    asm("{ .reg .u64 t; cvta.to.shared.u64 t, %1; cvt.u32.u64 %0, t; }" : "=r"(a) : "l"(p));
    return a;
}
__device__ __forceinline__ void cp16(uint32_t daddr, const void* src) {
    asm volatile("cp.async.cg.shared.global [%0], [%1], 16;" :: "r"(daddr), "l"(src));
}

// ---------------- K2: degrees + per-graph node counts ------------------------
__global__ void k_deg(const int* __restrict__ src, const int* __restrict__ dst,
                      const int* __restrict__ gids, int n_nodes, int n_edges) {
    int i = blockIdx.x * blockDim.x + threadIdx.x;
    int te = NREL * n_edges;
    if (i < te) {
        int r = i / n_edges;
        atomicAdd(&g_dego[r * n_nodes + src[i]], 1);
        atomicAdd(&g_degi[r * n_nodes + dst[i]], 1);
    } else if (i < te + n_nodes) {
        atomicAdd(&g_cnt[gids[i - te]], 1);
    }
}

// ---------------- K3: rsqrt tables, V_r = W2_r @ Wc, out init; deg reset ------
__global__ void k_prep(const float* __restrict__ W2, const float* __restrict__ Wc,
                       const float* __restrict__ b2, const float* __restrict__ bc,
                       float* __restrict__ out, int n_nodes, int n_graphs) {
    int i = blockIdx.x * blockDim.x + threadIdx.x;
    int t1 = NREL * n_nodes;
    if (i < t1) {
        g_rso[i] = rsqrtf((float)max(g_dego[i], 1));
        g_rsi[i] = rsqrtf((float)max(g_degi[i], 1));
        g_dego[i] = 0;                 // self-reset for next graph replay
        g_degi[i] = 0;
    } else if (i < t1 + NREL * HID * 2) {
        int v = i - t1;
        int r = v >> 6, f = (v >> 1) & 31, o = v & 1;
        float s = 0.f;
        #pragma unroll
        for (int j = 0; j < HID; j++) s += W2[r * (HID * HID) + f * HID + j] * Wc[j * 2 + o];
        g_V[v] = s;
    } else if (i < t1 + NREL * HID * 2 + 2 * n_graphs) {
        int u = i - t1 - NREL * HID * 2;
        int g = u >> 1, o = u & 1;
        if (o == 0) g_inv[g] = 1.f / (float)max(g_cnt[g], 1);
        float s = 0.f;
        for (int j = 0; j < HID; j++) {
            float bs = 0.f;
            #pragma unroll
            for (int r = 0; r < NREL; r++) bs += b2[r * HID + j];
            s += bs * Wc[j * 2 + o];
        }
        out[u] = bc[o] + (g_cnt[g] > 0 ? s : 0.f);   // empty graph -> pooled = 0
    }
}

// ---------------- K3b: W1 -> bf16 hi/lo image, [n][k] layout ------------------
__global__ void k_wconv(const float* __restrict__ W1) {
    int i = blockIdx.x * blockDim.x + threadIdx.x;   // 0..16383
    if (i >= 256 * 64) return;
    int n = i >> 6, kp = (i & 63);                   // col n, k pair index
    int k = kp * 2;
    int r = n >> 5, f = n & 31;
    float w0 = W1[r * (INF * HID) + k * HID + f];
    float w1 = W1[r * (INF * HID) + (k + 1) * HID + f];
    __nv_bfloat16 h0 = __float2bfloat16(w0);
    __nv_bfloat16 h1 = __float2bfloat16(w1);
    __nv_bfloat16 l0 = __float2bfloat16(w0 - __bfloat162float(h0));
    __nv_bfloat16 l1 = __float2bfloat16(w1 - __bfloat162float(h1));
    uint32_t off = (uint32_t)n * 256u + (uint32_t)k * 2u;
    __nv_bfloat162 hv; hv.x = h0; hv.y = h1;
    __nv_bfloat162 lv; lv.x = l0; lv.y = l1;
    *(__nv_bfloat162*)(g_wimg + off) = hv;
    *(__nv_bfloat162*)(g_wimg + 65536 + off) = lv;
}

// ---------------- K4: HMMA GEMM  y1 = x @ [W1_0..W1_7] ------------------------
// CTA: 128 nodes x 256 cols x FULL K=128 resident in smem (204KB, 1 CTA/SM).
// 512 threads, 16 warps (4M x 4N), warp tile 32x64. bf16 hi/lo split (3 MMA
// passes sharing fragments). B staged via cp.async (overlaps A load+convert);
// ONE __syncthreads, then an uninterrupted 8-step mainloop.
// Row stride 272B = 68 words: banks (row*68+w)%32 -> 8-row frag pattern hits
// {0,4,...,28}+w, conflict-free.
#define SROW  272
#define SA_H  0
#define SA_L  (128 * SROW)               // 34816
#define SB_H  (2 * 128 * SROW)           // 69632
#define SB_L  (SB_H + 256 * SROW)        // 139264
#define SMEM_G (SB_L + 256 * SROW)       // 208896

__device__ __forceinline__ void mma16816(float* c, const uint32_t* a, const uint32_t* b) {
    asm volatile("mma.sync.aligned.m16n8k16.row.col.f32.bf16.bf16.f32 "
        "{%0,%1,%2,%3}, {%4,%5,%6,%7}, {%8,%9}, {%0,%1,%2,%3};"
        : "+f"(c[0]), "+f"(c[1]), "+f"(c[2]), "+f"(c[3])
        : "r"(a[0]), "r"(a[1]), "r"(a[2]), "r"(a[3]), "r"(b[0]), "r"(b[1]));
}

__global__ __launch_bounds__(512, 1) void k_gemm_mma(const float* __restrict__ x,
                                                     int n_nodes) {
    extern __shared__ unsigned char smem[];
    uint32_t sb = smem_u32(smem);
    int t = threadIdx.x, wid = t >> 5, lid = t & 31;
    int gid = lid >> 2, tid4 = lid & 3;
    int node0 = blockIdx.x * 128;

    // ---- B: bulk cp.async of the pre-converted hi/lo image (async w.r.t. A) --
    {
        const unsigned char* bh = g_wimg;
        #pragma unroll
        for (int p = 0; p < 8; p++) {
            int idx = p * 512 + t;               // 0..4095
            int n = idx >> 4, c = idx & 15;
            uint32_t so = (uint32_t)n * 256u + (uint32_t)c * 16u;
            cp16(sb + SB_H + n * SROW + c * 16, bh + so);
            cp16(sb + SB_L + n * SROW + c * 16, bh + 65536 + so);
        }
        asm volatile("cp.async.commit_group;" ::: "memory");
    }
    // ---- A: load x, convert to bf16 hi/lo, store (overlaps B cp.async) -------
    #pragma unroll
    for (int p = 0; p < 8; p++) {
        int idx = p * 512 + t;                   // 0..4095
        int m = idx >> 5, k = (idx & 31) * 4;
        int gn = node0 + m;
        float4 v = make_float4(0.f, 0.f, 0.f, 0.f);
        if (gn < n_nodes) v = *(const float4*)(x + (size_t)gn * INF + k);
        __nv_bfloat16 h0 = __float2bfloat16(v.x), h1 = __float2bfloat16(v.y);
        __nv_bfloat16 h2 = __float2bfloat16(v.z), h3 = __float2bfloat16(v.w);
        __nv_bfloat16 l0 = __float2bfloat16(v.x - __bfloat162float(h0));
        __nv_bfloat16 l1 = __float2bfloat16(v.y - __bfloat162float(h1));
        __nv_bfloat16 l2 = __float2bfloat16(v.z - __bfloat162float(h2));
        __nv_bfloat16 l3 = __float2bfloat16(v.w - __bfloat162float(h3));
        __nv_bfloat162 a, b;
        a.x = h0; a.y = h1; b.x = h2; b.y = h3;
        uint2 hp; hp.x = *(uint32_t*)&a; hp.y = *(uint32_t*)&b;
        a.x = l0; a.y = l1; b.x = l2; b.y = l3;
        uint2 lp; lp.x = *(uint32_t*)&a; lp.y = *(uint32_t*)&b;
        *(uint2*)(smem + SA_H + m * SROW + k * 2) = hp;
        *(uint2*)(smem + SA_L + m * SROW + k * 2) = lp;
    }
    asm volatile("cp.async.wait_group 0;" ::: "memory");
    __syncthreads();

    int mrow0 = (wid & 3) * 32;          // 4 M-groups
    int ncol0 = (wid >> 2) * 64;         // 4 N-groups
    float acc[2][8][4];
    #pragma unroll
    for (int mi = 0; mi < 2; mi++)
        #pragma unroll
        for (int ni = 0; ni < 8; ni++)
            #pragma unroll
            for (int q = 0; q < 4; q++) acc[mi][ni][q] = 0.f;

    const unsigned char* aph = smem + SA_H + (mrow0 + gid) * SROW + tid4 * 4;
    const unsigned char* apl = smem + SA_L + (mrow0 + gid) * SROW + tid4 * 4;
    const unsigned char* bph = smem + SB_H + (ncol0 + gid) * SROW + tid4 * 4;
    const unsigned char* bpl = smem + SB_L + (ncol0 + gid) * SROW + tid4 * 4;
    #pragma unroll 2
    for (int ks = 0; ks < 8; ks++) {
        int kb = ks * 32;
        uint32_t ah[2][4], al[2][4];
        #pragma unroll
        for (int mi = 0; mi < 2; mi++) {
            const unsigned char* a0 = aph + mi * 16 * SROW + kb;
            ah[mi][0] = *(const uint32_t*)(a0);
            ah[mi][1] = *(const uint32_t*)(a0 + 8 * SROW);
            ah[mi][2] = *(const uint32_t*)(a0 + 16);
            ah[mi][3] = *(const uint32_t*)(a0 + 8 * SROW + 16);
            const unsigned char* a1 = apl + mi * 16 * SROW + kb;
            al[mi][0] = *(const uint32_t*)(a1);
            al[mi][1] = *(const uint32_t*)(a1 + 8 * SROW);
            al[mi][2] = *(const uint32_t*)(a1 + 16);
            al[mi][3] = *(const uint32_t*)(a1 + 8 * SROW + 16);
        }
        #pragma unroll
        for (int ni = 0; ni < 8; ni++) {
            const unsigned char* b0 = bph + ni * 8 * SROW + kb;
            const unsigned char* b1 = bpl + ni * 8 * SROW + kb;
            uint32_t bh2[2], bl2[2];
            bh2[0] = *(const uint32_t*)(b0);
            bh2[1] = *(const uint32_t*)(b0 + 16);
            bl2[0] = *(const uint32_t*)(b1);
            bl2[1] = *(const uint32_t*)(b1 + 16);
            #pragma unroll
            for (int mi = 0; mi < 2; mi++) {
                mma16816(acc[mi][ni], ah[mi], bh2);   // hi*hi
                mma16816(acc[mi][ni], al[mi], bh2);   // lo*hi
                mma16816(acc[mi][ni], ah[mi], bl2);   // hi*lo
            }
        }
    }

    // ---- epilogue: write y1 ----------------------------------------------------
    #pragma unroll
    for (int mi = 0; mi < 2; mi++) {
        int r0 = node0 + mrow0 + mi * 16 + gid;
        #pragma unroll
        for (int ni = 0; ni < 8; ni++) {
            int col = ncol0 + ni * 8 + tid4 * 2;
            if (r0 < n_nodes)
                *(float2*)(g_y1 + (size_t)r0 * NCOLS + col) =
                    make_float2(acc[mi][ni][0], acc[mi][ni][1]);
            if (r0 + 8 < n_nodes)
                *(float2*)(g_y1 + (size_t)(r0 + 8) * NCOLS + col) =
                    make_float2(acc[mi][ni][2], acc[mi][ni][3]);
        }
    }
}

// ---------------- K5: layer-1 edge scatter (both deg scales folded) ----------
__global__ void k_scatter1(const int* __restrict__ src, const int* __restrict__ dst,
                           int n_nodes, int n_edges) {
    int i = blockIdx.x * blockDim.x + threadIdx.x;
    int tot = NREL * n_edges * 8;
    if (i >= tot) return;
    int e = i >> 3, q = i & 7;
    int r = e / n_edges;
    int s = src[e], d = dst[e];
    float sc = g_rso[r * n_nodes + s] * g_rsi[r * n_nodes + d];
    float4 v = *(const float4*)(g_y1 + (size_t)s * NCOLS + r * HID + q * 4);
    v.x *= sc; v.y *= sc; v.z *= sc; v.w *= sc;
    atomicAdd((float4*)(g_h1 + (size_t)d * HID + q * 4), v);
}

// ---------------- K6: bias + relu (h1 -> h1b); resets h1 and cnt --------------
__global__ void k_relu(const float* __restrict__ b1, int n_nodes) {
    __shared__ float bs[HID];
    if (threadIdx.x < HID) {
        float s = 0.f;
        #pragma unroll
        for (int r = 0; r < NREL; r++) s += b1[r * HID + threadIdx.x];
        bs[threadIdx.x] = s;
    }
    __syncthreads();
    int i = blockIdx.x * blockDim.x + threadIdx.x;
    if (i < n_nodes * HID) {
        g_h1b[i] = fmaxf(g_h1[i] + bs[i & 31], 0.f);
        g_h1[i] = 0.f;                  // self-reset for next graph replay
    }
    if (blockIdx.x == 0 && threadIdx.x < NGMAX) g_cnt[threadIdx.x] = 0;
}

// -------- K7: fused layer-2 + mean-pool + classifier (edge -> out[64,2]) -----
__global__ __launch_bounds__(256) void k_scatter2(const int* __restrict__ src,
                                                  const int* __restrict__ dst,
                                                  const int* __restrict__ gids,
                                                  float* __restrict__ out,
                                                  int n_nodes, int n_edges) {
    __shared__ float zs[NGMAX * 2];
    __shared__ float Vs[NREL * HID * 2];
    __shared__ float inv_s[NGMAX];
    int t = threadIdx.x;
    if (t < NGMAX * 2) zs[t] = 0.f;
    for (int i = t; i < NREL * HID * 2; i += 256) Vs[i] = g_V[i];
    if (t < NGMAX) inv_s[t] = g_inv[t];
    __syncthreads();

    int te = NREL * n_edges;
    int e0 = blockIdx.x * EPB;
    #pragma unroll
    for (int it = 0; it < EPB / 256; it++) {
        int e = e0 + it * 256 + t;
        if (e < te) {
            int r = e / n_edges;
            int s = src[e], d = dst[e];
            int g = gids[d];
            float coeff = g_rso[r * n_nodes + s] * g_rsi[r * n_nodes + d] * inv_s[g];
            const float4* hp = (const float4*)(g_h1b + (size_t)s * HID);
            const float* vp = Vs + r * (HID * 2);
            float a0 = 0.f, a1 = 0.f;
            #pragma unroll
            for (int q = 0; q < 8; q++) {
                float4 hv = hp[q];
                a0 += hv.x * vp[q * 8 + 0] + hv.y * vp[q * 8 + 2] +
                      hv.z * vp[q * 8 + 4] + hv.w * vp[q * 8 + 6];
                a1 += hv.x * vp[q * 8 + 1] + hv.y * vp[q * 8 + 3] +
                      hv.z * vp[q * 8 + 5] + hv.w * vp[q * 8 + 7];
            }
            atomicAdd(&zs[g * 2 + 0], a0 * coeff);
            atomicAdd(&zs[g * 2 + 1], a1 * coeff);
        }
    }
    __syncthreads();
    if (t < NGMAX * 2) atomicAdd(&out[t], zs[t]);
}

// ---------------- launch ------------------------------------------------------
extern "C" void kernel_launch(void* const* d_in, const int* in_sizes, int n_in,
                              void* d_out, int out_size) {
    int off = (n_in >= 11) ? 1 : 0;
    const float* x   = (const float*)d_in[0];
    const int*   src = (const int*)d_in[1];
    const int*   dst = (const int*)d_in[2];
    const int*   gid = (const int*)d_in[3];
    const float* W1  = (const float*)d_in[4 + off];
    const float* b1  = (const float*)d_in[5 + off];
    const float* W2  = (const float*)d_in[6 + off];
    const float* b2  = (const float*)d_in[7 + off];
    const float* Wc  = (const float*)d_in[8 + off];
    const float* bc  = (const float*)d_in[9 + off];
    float* out = (float*)d_out;

    int n_nodes  = in_sizes[3];
    int n_edges  = in_sizes[1] / NREL;
    int n_graphs = out_size / 2;

    cudaFuncSetAttribute(k_gemm_mma, cudaFuncAttributeMaxDynamicSharedMemorySize,
                         SMEM_G);

    k_wconv<<<64, 256>>>(W1);

    int tot1 = NREL * n_edges + n_nodes;
    k_deg<<<(tot1 + 255) / 256, 256>>>(src, dst, gid, n_nodes, n_edges);

    int tot2 = NREL * n_nodes + NREL * HID * 2 + 2 * n_graphs;
    k_prep<<<(tot2 + 255) / 256, 256>>>(W2, Wc, b2, bc, out, n_nodes, n_graphs);

    k_gemm_mma<<<(n_nodes + 127) / 128, 512, SMEM_G>>>(x, n_nodes);

    int tot5 = NREL * n_edges * 8;
    k_scatter1<<<(tot5 + 255) / 256, 256>>>(src, dst, n_nodes, n_edges);

    int tot6 = HID * n_nodes;
    k_relu<<<(tot6 + 255) / 256, 256>>>(b1, n_nodes);

    k_scatter2<<<(NREL * n_edges + EPB - 1) / EPB, 256>>>(src, dst, gid, out,
                                                          n_nodes, n_edges);
}

// round 9
// speedup vs baseline: 1.2080x; 1.0110x over previous
#include <cuda_runtime.h>
#include <cuda_bf16.h>
#include <cstdint>

// ---------------- problem-size constants (fixed by this problem) -------------
#define MAXN   100000
#define NREL   8
#define INF    128
#define HID    32
#define NCOLS  (NREL*HID)      // 256
#define NGMAX  64
#define EPB    1024            // edges per block in scatter2

// ---------------- device scratch (static: no allocations allowed) ------------
// Self-reset for graph replay: zero at module load; every consumer kernel
// resets what it consumed so the next replay sees zeros again.
__device__ __align__(128) float g_y1[(size_t)MAXN * NCOLS];   // x @ [W1_0..W1_7]
__device__ __align__(128) float g_h1[(size_t)MAXN * HID];     // scatter1 accum (reset by k_relu)
__device__ __align__(128) float g_h1b[(size_t)MAXN * HID];    // relu output
__device__ __align__(128) float g_rso[NREL * MAXN];           // rsqrt(max(deg_out,1))
__device__ __align__(128) float g_rsi[NREL * MAXN];           // rsqrt(max(deg_in,1))
__device__ __align__(128) int   g_dego[NREL * MAXN];          // reset by k_prep
__device__ __align__(128) int   g_degi[NREL * MAXN];          // reset by k_prep
__device__ __align__(128) int   g_cnt[NGMAX];                 // reset by k_relu
__device__ __align__(128) float g_inv[NGMAX];                 // 1/max(cnt,1)
__device__ __align__(128) float g_V[NREL * HID * 2];          // W2_r @ Wc
// bf16 hi/lo weight image, [n][k] layout (k contiguous, 256B/row):
// [0,64K) = B_hi (256 n-rows x 128 k), [64K,128K) = B_lo
__device__ __align__(128) unsigned char g_wimg[131072];

__device__ __forceinline__ uint32_t smem_u32(const void* p) {
    uint32_t a;
    asm("{ .reg .u64 t; cvta.to.shared.u64 t, %1; cvt.u32.u64 %0, t; }" : "=r"(a) : "l"(p));
    return a;
}
__device__ __forceinline__ void cp16(uint32_t daddr, const void* src) {
    asm volatile("cp.async.cg.shared.global [%0], [%1], 16;" :: "r"(daddr), "l"(src));
}
__device__ __forceinline__ void ldsm4(uint32_t* r, uint32_t addr) {
    asm volatile("ldmatrix.sync.aligned.m8n8.x4.shared.b16 {%0,%1,%2,%3}, [%4];"
        : "=r"(r[0]), "=r"(r[1]), "=r"(r[2]), "=r"(r[3]) : "r"(addr));
}

// ---------------- K2: wconv (blocks 0-63) + degrees + graph counts ------------
__global__ void k_deg(const int* __restrict__ src, const int* __restrict__ dst,
                      const int* __restrict__ gids, const float* __restrict__ W1,
                      int n_nodes, int n_edges) {
    if (blockIdx.x < 64) {
        // W1 -> bf16 hi/lo image, [n][k] layout
        int i = blockIdx.x * blockDim.x + threadIdx.x;   // 0..16383
        int n = i >> 6, k = (i & 63) * 2;
        int r = n >> 5, f = n & 31;
        float w0 = W1[r * (INF * HID) + k * HID + f];
        float w1 = W1[r * (INF * HID) + (k + 1) * HID + f];
        __nv_bfloat16 h0 = __float2bfloat16(w0);
        __nv_bfloat16 h1 = __float2bfloat16(w1);
        __nv_bfloat16 l0 = __float2bfloat16(w0 - __bfloat162float(h0));
        __nv_bfloat16 l1 = __float2bfloat16(w1 - __bfloat162float(h1));
        uint32_t off = (uint32_t)n * 256u + (uint32_t)k * 2u;
        __nv_bfloat162 hv; hv.x = h0; hv.y = h1;
        __nv_bfloat162 lv; lv.x = l0; lv.y = l1;
        *(__nv_bfloat162*)(g_wimg + off) = hv;
        *(__nv_bfloat162*)(g_wimg + 65536 + off) = lv;
        return;
    }
    int i = (blockIdx.x - 64) * blockDim.x + threadIdx.x;
    int te = NREL * n_edges;
    if (i < te) {
        int r = i / n_edges;
        atomicAdd(&g_dego[r * n_nodes + src[i]], 1);
        atomicAdd(&g_degi[r * n_nodes + dst[i]], 1);
    } else if (i < te + n_nodes) {
        atomicAdd(&g_cnt[gids[i - te]], 1);
    }
}

// ---------------- K3: rsqrt tables, V_r = W2_r @ Wc, out init; deg reset ------
__global__ void k_prep(const float* __restrict__ W2, const float* __restrict__ Wc,
                       const float* __restrict__ b2, const float* __restrict__ bc,
                       float* __restrict__ out, int n_nodes, int n_graphs) {
    int i = blockIdx.x * blockDim.x + threadIdx.x;
    int t1 = NREL * n_nodes;
    if (i < t1) {
        g_rso[i] = rsqrtf((float)max(g_dego[i], 1));
        g_rsi[i] = rsqrtf((float)max(g_degi[i], 1));
        g_dego[i] = 0;                 // self-reset for next graph replay
        g_degi[i] = 0;
    } else if (i < t1 + NREL * HID * 2) {
        int v = i - t1;
        int r = v >> 6, f = (v >> 1) & 31, o = v & 1;
        float s = 0.f;
        #pragma unroll
        for (int j = 0; j < HID; j++) s += W2[r * (HID * HID) + f * HID + j] * Wc[j * 2 + o];
        g_V[v] = s;
    } else if (i < t1 + NREL * HID * 2 + 2 * n_graphs) {
        int u = i - t1 - NREL * HID * 2;
        int g = u >> 1, o = u & 1;
        if (o == 0) g_inv[g] = 1.f / (float)max(g_cnt[g], 1);
        float s = 0.f;
        for (int j = 0; j < HID; j++) {
            float bs = 0.f;
            #pragma unroll
            for (int r = 0; r < NREL; r++) bs += b2[r * HID + j];
            s += bs * Wc[j * 2 + o];
        }
        out[u] = bc[o] + (g_cnt[g] > 0 ? s : 0.f);   // empty graph -> pooled = 0
    }
}

// ---------------- K4: HMMA GEMM  y1 = x @ [W1_0..W1_7] ------------------------
// CTA: 128 nodes x 256 cols x FULL K=128 resident in smem (204KB, 1 CTA/SM).
// 512 threads, 16 warps (4M x 4N), warp tile 32x64. bf16 hi/lo split (3 MMA
// passes sharing fragments). All fragment loads via ldmatrix.x4 (12 LDSM/k-step
// vs 48 LDS.32). Row stride 272B keeps every 8-row ldmatrix wavefront
// conflict-free ((68*row) mod 32 covers all 4-word groups).
#define SROW  272
#define SA_H  0
#define SA_L  (128 * SROW)               // 34816
#define SB_H  (2 * 128 * SROW)           // 69632
#define SB_L  (SB_H + 256 * SROW)        // 139264
#define SMEM_G (SB_L + 256 * SROW)       // 208896

__device__ __forceinline__ void mma16816(float* c, const uint32_t* a, const uint32_t* b) {
    asm volatile("mma.sync.aligned.m16n8k16.row.col.f32.bf16.bf16.f32 "
        "{%0,%1,%2,%3}, {%4,%5,%6,%7}, {%8,%9}, {%0,%1,%2,%3};"
        : "+f"(c[0]), "+f"(c[1]), "+f"(c[2]), "+f"(c[3])
        : "r"(a[0]), "r"(a[1]), "r"(a[2]), "r"(a[3]), "r"(b[0]), "r"(b[1]));
}

__global__ __launch_bounds__(512, 1) void k_gemm_mma(const float* __restrict__ x,
                                                     int n_nodes) {
    extern __shared__ unsigned char smem[];
    uint32_t sb = smem_u32(smem);
    int t = threadIdx.x, wid = t >> 5, lid = t & 31;
    int gid = lid >> 2, tid4 = lid & 3;
    int node0 = blockIdx.x * 128;

    // ---- B: bulk cp.async of the pre-converted hi/lo image (async w.r.t. A) --
    {
        const unsigned char* bh = g_wimg;
        #pragma unroll
        for (int p = 0; p < 8; p++) {
            int idx = p * 512 + t;               // 0..4095
            int n = idx >> 4, c = idx & 15;
            uint32_t so = (uint32_t)n * 256u + (uint32_t)c * 16u;
            cp16(sb + SB_H + n * SROW + c * 16, bh + so);
            cp16(sb + SB_L + n * SROW + c * 16, bh + 65536 + so);
        }
        asm volatile("cp.async.commit_group;" ::: "memory");
    }
    // ---- A: load x, convert to bf16 hi/lo, store (overlaps B cp.async) -------
    #pragma unroll
    for (int p = 0; p < 8; p++) {
        int idx = p * 512 + t;                   // 0..4095
        int m = idx >> 5, k = (idx & 31) * 4;
        int gn = node0 + m;
        float4 v = make_float4(0.f, 0.f, 0.f, 0.f);
        if (gn < n_nodes) v = *(const float4*)(x + (size_t)gn * INF + k);
        __nv_bfloat16 h0 = __float2bfloat16(v.x), h1 = __float2bfloat16(v.y);
        __nv_bfloat16 h2 = __float2bfloat16(v.z), h3 = __float2bfloat16(v.w);
        __nv_bfloat16 l0 = __float2bfloat16(v.x - __bfloat162float(h0));
        __nv_bfloat16 l1 = __float2bfloat16(v.y - __bfloat162float(h1));
        __nv_bfloat16 l2 = __float2bfloat16(v.z - __bfloat162float(h2));
        __nv_bfloat16 l3 = __float2bfloat16(v.w - __bfloat162float(h3));
        __nv_bfloat162 a, b;
        a.x = h0; a.y = h1; b.x = h2; b.y = h3;
        uint2 hp; hp.x = *(uint32_t*)&a; hp.y = *(uint32_t*)&b;
        a.x = l0; a.y = l1; b.x = l2; b.y = l3;
        uint2 lp; lp.x = *(uint32_t*)&a; lp.y = *(uint32_t*)&b;
        *(uint2*)(smem + SA_H + m * SROW + k * 2) = hp;
        *(uint2*)(smem + SA_L + m * SROW + k * 2) = lp;
    }
    asm volatile("cp.async.wait_group 0;" ::: "memory");
    __syncthreads();

    int mrow0 = (wid & 3) * 32;          // 4 M-groups
    int ncol0 = (wid >> 2) * 64;         // 4 N-groups
    float acc[2][8][4];
    #pragma unroll
    for (int mi = 0; mi < 2; mi++)
        #pragma unroll
        for (int ni = 0; ni < 8; ni++)
            #pragma unroll
            for (int q = 0; q < 4; q++) acc[mi][ni][q] = 0.f;

    // ldmatrix per-lane addresses.
    // A (m16k16, matrices {m0-7,k0},{m8-15,k0},{m0-7,+16B},{m8-15,+16B}):
    int l3 = lid & 7, grp = lid >> 3;
    uint32_t a_row = mrow0 + l3 + (grp & 1) * 8;
    uint32_t a_koff = (grp >> 1) * 16;
    uint32_t aH0 = sb + SA_H + a_row * SROW + a_koff;
    uint32_t aH1 = aH0 + 16 * SROW;
    uint32_t aL0 = aH0 + (SA_L - SA_H);
    uint32_t aL1 = aH1 + (SA_L - SA_H);
    // B pair (ni, ni+1): matrices {n0-7,k0},{n0-7,+16B},{n8-15,k0},{n8-15,+16B}
    //   -> r0,r1 = b(ni), r2,r3 = b(ni+1)
    uint32_t b_row = ncol0 + l3 + (grp >> 1) * 8;
    uint32_t b_koff = (grp & 1) * 16;
    uint32_t bH = sb + SB_H + b_row * SROW + b_koff;
    uint32_t bL = bH + (SB_L - SB_H);

    #pragma unroll
    for (int ks = 0; ks < 8; ks++) {
        uint32_t kb = ks * 32;
        uint32_t ah[2][4], al[2][4];
        ldsm4(ah[0], aH0 + kb);
        ldsm4(ah[1], aH1 + kb);
        ldsm4(al[0], aL0 + kb);
        ldsm4(al[1], aL1 + kb);
        #pragma unroll
        for (int p = 0; p < 4; p++) {        // ni pair = (2p, 2p+1)
            uint32_t bh4[4], bl4[4];
            ldsm4(bh4, bH + p * 16 * SROW + kb);
            ldsm4(bl4, bL + p * 16 * SROW + kb);
            #pragma unroll
            for (int h = 0; h < 2; h++) {    // ni = 2p + h
                int ni = 2 * p + h;
                uint32_t bh2[2] = { bh4[2 * h], bh4[2 * h + 1] };
                uint32_t bl2[2] = { bl4[2 * h], bl4[2 * h + 1] };
                #pragma unroll
                for (int mi = 0; mi < 2; mi++) {
                    mma16816(acc[mi][ni], ah[mi], bh2);   // hi*hi
                    mma16816(acc[mi][ni], al[mi], bh2);   // lo*hi
                    mma16816(acc[mi][ni], ah[mi], bl2);   // hi*lo
                }
            }
        }
    }

    // ---- epilogue: write y1 ----------------------------------------------------
    #pragma unroll
    for (int mi = 0; mi < 2; mi++) {
        int r0 = node0 + mrow0 + mi * 16 + gid;
        #pragma unroll
        for (int ni = 0; ni < 8; ni++) {
            int col = ncol0 + ni * 8 + tid4 * 2;
            if (r0 < n_nodes)
                *(float2*)(g_y1 + (size_t)r0 * NCOLS + col) =
                    make_float2(acc[mi][ni][0], acc[mi][ni][1]);
            if (r0 + 8 < n_nodes)
                *(float2*)(g_y1 + (size_t)(r0 + 8) * NCOLS + col) =
                    make_float2(acc[mi][ni][2], acc[mi][ni][3]);
        }
    }
}

// ---------------- K5: layer-1 edge scatter (both deg scales folded) ----------
__global__ void k_scatter1(const int* __restrict__ src, const int* __restrict__ dst,
                           int n_nodes, int n_edges) {
    int i = blockIdx.x * blockDim.x + threadIdx.x;
    int tot = NREL * n_edges * 8;
    if (i >= tot) return;
    int e = i >> 3, q = i & 7;
    int r = e / n_edges;
    int s = src[e], d = dst[e];
    float sc = g_rso[r * n_nodes + s] * g_rsi[r * n_nodes + d];
    float4 v = *(const float4*)(g_y1 + (size_t)s * NCOLS + r * HID + q * 4);
    v.x *= sc; v.y *= sc; v.z *= sc; v.w *= sc;
    atomicAdd((float4*)(g_h1 + (size_t)d * HID + q * 4), v);
}

// ---------------- K6: bias + relu (h1 -> h1b); resets h1 and cnt --------------
__global__ void k_relu(const float* __restrict__ b1, int n_nodes) {
    __shared__ float bs[HID];
    if (threadIdx.x < HID) {
        float s = 0.f;
        #pragma unroll
        for (int r = 0; r < NREL; r++) s += b1[r * HID + threadIdx.x];
        bs[threadIdx.x] = s;
    }
    __syncthreads();
    int i = blockIdx.x * blockDim.x + threadIdx.x;
    if (i < n_nodes * HID) {
        g_h1b[i] = fmaxf(g_h1[i] + bs[i & 31], 0.f);
        g_h1[i] = 0.f;                  // self-reset for next graph replay
    }
    if (blockIdx.x == 0 && threadIdx.x < NGMAX) g_cnt[threadIdx.x] = 0;
}

// -------- K7: fused layer-2 + mean-pool + classifier (edge -> out[64,2]) -----
__global__ __launch_bounds__(256) void k_scatter2(const int* __restrict__ src,
                                                  const int* __restrict__ dst,
                                                  const int* __restrict__ gids,
                                                  float* __restrict__ out,
                                                  int n_nodes, int n_edges) {
    __shared__ float zs[NGMAX * 2];
    __shared__ float Vs[NREL * HID * 2];
    __shared__ float inv_s[NGMAX];
    int t = threadIdx.x;
    if (t < NGMAX * 2) zs[t] = 0.f;
    for (int i = t; i < NREL * HID * 2; i += 256) Vs[i] = g_V[i];
    if (t < NGMAX) inv_s[t] = g_inv[t];
    __syncthreads();

    int te = NREL * n_edges;
    int e0 = blockIdx.x * EPB;
    #pragma unroll
    for (int it = 0; it < EPB / 256; it++) {
        int e = e0 + it * 256 + t;
        if (e < te) {
            int r = e / n_edges;
            int s = src[e], d = dst[e];
            int g = gids[d];
            float coeff = g_rso[r * n_nodes + s] * g_rsi[r * n_nodes + d] * inv_s[g];
            const float4* hp = (const float4*)(g_h1b + (size_t)s * HID);
            const float* vp = Vs + r * (HID * 2);
            float a0 = 0.f, a1 = 0.f;
            #pragma unroll
            for (int q = 0; q < 8; q++) {
                float4 hv = hp[q];
                a0 += hv.x * vp[q * 8 + 0] + hv.y * vp[q * 8 + 2] +
                      hv.z * vp[q * 8 + 4] + hv.w * vp[q * 8 + 6];
                a1 += hv.x * vp[q * 8 + 1] + hv.y * vp[q * 8 + 3] +
                      hv.z * vp[q * 8 + 5] + hv.w * vp[q * 8 + 7];
            }
            atomicAdd(&zs[g * 2 + 0], a0 * coeff);
            atomicAdd(&zs[g * 2 + 1], a1 * coeff);
        }
    }
    __syncthreads();
    if (t < NGMAX * 2) atomicAdd(&out[t], zs[t]);
}

// ---------------- launch ------------------------------------------------------
extern "C" void kernel_launch(void* const* d_in, const int* in_sizes, int n_in,
                              void* d_out, int out_size) {
    int off = (n_in >= 11) ? 1 : 0;
    const float* x   = (const float*)d_in[0];
    const int*   src = (const int*)d_in[1];
    const int*   dst = (const int*)d_in[2];
    const int*   gid = (const int*)d_in[3];
    const float* W1  = (const float*)d_in[4 + off];
    const float* b1  = (const float*)d_in[5 + off];
    const float* W2  = (const float*)d_in[6 + off];
    const float* b2  = (const float*)d_in[7 + off];
    const float* Wc  = (const float*)d_in[8 + off];
    const float* bc  = (const float*)d_in[9 + off];
    float* out = (float*)d_out;

    int n_nodes  = in_sizes[3];
    int n_edges  = in_sizes[1] / NREL;
    int n_graphs = out_size / 2;

    cudaFuncSetAttribute(k_gemm_mma, cudaFuncAttributeMaxDynamicSharedMemorySize,
                         SMEM_G);

    int tot1 = NREL * n_edges + n_nodes;
    k_deg<<<64 + (tot1 + 255) / 256, 256>>>(src, dst, gid, W1, n_nodes, n_edges);

    int tot2 = NREL * n_nodes + NREL * HID * 2 + 2 * n_graphs;
    k_prep<<<(tot2 + 255) / 256, 256>>>(W2, Wc, b2, bc, out, n_nodes, n_graphs);

    k_gemm_mma<<<(n_nodes + 127) / 128, 512, SMEM_G>>>(x, n_nodes);

    int tot5 = NREL * n_edges * 8;
    k_scatter1<<<(tot5 + 255) / 256, 256>>>(src, dst, n_nodes, n_edges);

    int tot6 = HID * n_nodes;
    k_relu<<<(tot6 + 255) / 256, 256>>>(b1, n_nodes);

    k_scatter2<<<(NREL * n_edges + EPB - 1) / EPB, 256>>>(src, dst, gid, out,
                                                          n_nodes, n_edges);
}